// round 8
// baseline (speedup 1.0000x reference)
#include <cuda_runtime.h>
#include <cuda_bf16.h>
#include <cstdint>

// NT-Xent loss. Primary: tcgen05 bf16 GEMM (TS mode: A in TMEM, B in SMEM)
// + fused masked logsumexp, last-CTA in-kernel final reduction (sm_103a pass).
// Fallback: SIMT fp32 tiled GEMM (non-'a' passes) + separate tail kernel.

#define TWO_N   8192
#define NHALF   4096
#define DIMK    256
#define TM      128
#define TN      128
#define NTILE   32          // col tiles per CTA (4096 / 128)
#define NTHREADS 416        // 8 epi + 1 mma + 4 loader warps
#define NWARPS  13
#define IDESC   0x8200490u  // f32 accum, bf16 x bf16, N=128, M=128

#define B_OFF   0           // three 64KB B buffers
#define CTRL_OFF 196608     // tmem ptr (4B)
#define MB_OFF  196616      // mbarriers: b_full[3], mma[3], epi[3] (8B each)
#define SMEM_TOTAL 196704

// TMEM columns: A at [0,128), D buffers at 128 + d*128, d in {0,1,2}
#define TMEM_D0 128

// SIMT fallback tiling
#define BM      64
#define BN      64
#define PAD     260
#define SIMT_SMEM ((BM + BN) * PAD * 4)

// Feature gate: tcgen05 only exists in the arch-specific sm_103a pass.
#if defined(__CUDA_ARCH__) && (defined(__CUDA_ARCH_FEAT_SM103_ALL) || \
    (defined(__CUDA_ARCH_SPECIFIC__) && (__CUDA_ARCH_SPECIFIC__ == 1030)))
#define TC_OK 1
#else
#define TC_OK 0
#endif

__device__ uint4 g_Rb4[TWO_N * DIMK / 8];   // bf16 normalized reps (4 MB)
__device__ float g_R[TWO_N * DIMK];         // fp32 normalized reps (fallback)
__device__ float g_s[2 * TWO_N];
__device__ float g_p[2 * TWO_N];
__device__ float g_partials[64];
__device__ int   g_ticket;

// ---------------- generic helpers ----------------
__device__ __forceinline__ uint32_t smem_u32(const void* p) {
    uint32_t a;
    asm("{ .reg .u64 t; cvta.to.shared.u64 t, %1; cvt.u32.u64 %0, t; }" : "=r"(a) : "l"(p));
    return a;
}

#if TC_OK
// ---------------- tcgen05 / PTX helpers (sm_103a pass only) ----------------
__device__ __forceinline__ uint32_t elect_one() {
    uint32_t p;
    asm volatile("{ .reg .pred p; elect.sync _|p, 0xFFFFFFFF; selp.b32 %0,1,0,p; }" : "=r"(p));
    return p;
}
__device__ __forceinline__ void mb_init(uint32_t mb, uint32_t cnt) {
    asm volatile("mbarrier.init.shared.b64 [%0], %1;" :: "r"(mb), "r"(cnt) : "memory");
}
__device__ __forceinline__ void mb_arrive(uint32_t mb) {
    asm volatile("mbarrier.arrive.shared.b64 _, [%0];" :: "r"(mb) : "memory");
}
__device__ __forceinline__ void mb_waitp(uint32_t mb, uint32_t parity) {
    asm volatile(
        "{\n\t.reg .pred P1;\n\t"
        "WL_%=:\n\t"
        "mbarrier.try_wait.parity.acquire.cta.shared::cta.b64 P1, [%0], %1, 0x989680;\n\t"
        "@P1 bra.uni WD_%=;\n\t"
        "bra.uni WL_%=;\n\t"
        "WD_%=:\n\t}"
        :: "r"(mb), "r"(parity) : "memory");
}
__device__ __forceinline__ void fence_async_shared() {
    asm volatile("fence.proxy.async.shared::cta;" ::: "memory");
}
__device__ __forceinline__ void cp_async16(uint32_t dst, const void* src) {
    asm volatile("cp.async.cg.shared.global [%0], [%1], 16;"
                 :: "r"(dst), "l"(src) : "memory");
}
__device__ __forceinline__ void cp_async_commit_wait() {
    asm volatile("cp.async.commit_group;" ::: "memory");
    asm volatile("cp.async.wait_group 0;" ::: "memory");
}
#define TC_FENCE_AFTER()  asm volatile("tcgen05.fence::after_thread_sync;" ::: "memory")
#define TC_FENCE_BEFORE() asm volatile("tcgen05.fence::before_thread_sync;" ::: "memory")
#define TC_WAIT_LD()      asm volatile("tcgen05.wait::ld.sync.aligned;" ::: "memory")
#define TC_WAIT_ST()      asm volatile("tcgen05.wait::st.sync.aligned;" ::: "memory")

__device__ __forceinline__ void tc_alloc(uint32_t smem_res, uint32_t ncols) {
    asm volatile("tcgen05.alloc.cta_group::1.sync.aligned.shared::cta.b32 [%0], %1;"
                 :: "r"(smem_res), "r"(ncols) : "memory");
}
__device__ __forceinline__ void tc_dealloc(uint32_t tmem, uint32_t ncols) {
    asm volatile("tcgen05.dealloc.cta_group::1.sync.aligned.b32 %0, %1;" :: "r"(tmem), "r"(ncols));
}
__device__ __forceinline__ void tc_commit(uint32_t mb) {
    asm volatile("tcgen05.commit.cta_group::1.mbarrier::arrive::one.shared::cluster.b64 [%0];"
                 :: "r"(mb) : "memory");
}
// TS-mode MMA: A from TMEM, B via SMEM descriptor.
__device__ __forceinline__ void mma_f16_ts(uint32_t d, uint32_t a_tmem, uint64_t b,
                                           uint32_t idesc, uint32_t en) {
    asm volatile(
        "{\n\t.reg .pred p;\n\tsetp.ne.u32 p, %5, 0;\n\t"
        "tcgen05.mma.cta_group::1.kind::f16 [%0], [%1], %2, %3, {%4,%4,%4,%4}, p;\n\t}"
        :: "r"(d), "r"(a_tmem), "l"(b), "r"(idesc), "r"(0u), "r"(en) : "memory");
}

#define LDTM_X32(r, tmem) \
    asm volatile("tcgen05.ld.sync.aligned.32x32b.x32.b32 " \
        "{%0,%1,%2,%3,%4,%5,%6,%7,%8,%9,%10,%11,%12,%13,%14,%15," \
        "%16,%17,%18,%19,%20,%21,%22,%23,%24,%25,%26,%27,%28,%29,%30,%31}, [%32];" \
        : "=r"((r)[0]),"=r"((r)[1]),"=r"((r)[2]),"=r"((r)[3]),"=r"((r)[4]),"=r"((r)[5]), \
          "=r"((r)[6]),"=r"((r)[7]),"=r"((r)[8]),"=r"((r)[9]),"=r"((r)[10]),"=r"((r)[11]), \
          "=r"((r)[12]),"=r"((r)[13]),"=r"((r)[14]),"=r"((r)[15]),"=r"((r)[16]),"=r"((r)[17]), \
          "=r"((r)[18]),"=r"((r)[19]),"=r"((r)[20]),"=r"((r)[21]),"=r"((r)[22]),"=r"((r)[23]), \
          "=r"((r)[24]),"=r"((r)[25]),"=r"((r)[26]),"=r"((r)[27]),"=r"((r)[28]),"=r"((r)[29]), \
          "=r"((r)[30]),"=r"((r)[31]) : "r"(tmem))

#define STTM_X32(tmem, r) \
    asm volatile("tcgen05.st.sync.aligned.32x32b.x32.b32 [%0], " \
        "{%1,%2,%3,%4,%5,%6,%7,%8,%9,%10,%11,%12,%13,%14,%15,%16," \
        "%17,%18,%19,%20,%21,%22,%23,%24,%25,%26,%27,%28,%29,%30,%31,%32};" \
        :: "r"(tmem), \
           "r"((r)[0]),"r"((r)[1]),"r"((r)[2]),"r"((r)[3]),"r"((r)[4]),"r"((r)[5]), \
           "r"((r)[6]),"r"((r)[7]),"r"((r)[8]),"r"((r)[9]),"r"((r)[10]),"r"((r)[11]), \
           "r"((r)[12]),"r"((r)[13]),"r"((r)[14]),"r"((r)[15]),"r"((r)[16]),"r"((r)[17]), \
           "r"((r)[18]),"r"((r)[19]),"r"((r)[20]),"r"((r)[21]),"r"((r)[22]),"r"((r)[23]), \
           "r"((r)[24]),"r"((r)[25]),"r"((r)[26]),"r"((r)[27]),"r"((r)[28]),"r"((r)[29]), \
           "r"((r)[30]),"r"((r)[31]) : "memory")

// SW128 base descriptor (version=1, LBO=1, SBO=64) + start address
__device__ __forceinline__ uint64_t mk_desc(uint32_t addr) {
    uint64_t base = (uint64_t(2) << 61) | (uint64_t(1) << 46) | (uint64_t(64) << 32)
                  | (uint64_t(1) << 16);
    return base | ((uint64_t)(addr >> 4) & 0x3FFF);
}

// packed f32x2 helpers
#define PK2(d, lo, hi) asm("mov.b64 %0,{%1,%2};" : "=l"(d) : "r"(lo), "r"(hi))
#define UPK2(lo, hi, s) asm("mov.b64 {%0,%1},%2;" : "=r"(lo), "=r"(hi) : "l"(s))
#define FMA2(d, a, b, c) asm("fma.rn.f32x2 %0,%1,%2,%3;" : "=l"(d) : "l"(a), "l"(b), "l"(c))
#define ADD2(d, a, b)    asm("add.rn.f32x2 %0,%1,%2;" : "=l"(d) : "l"(a), "l"(b))
__device__ __forceinline__ uint64_t pk2c(float v) {
    uint64_t r; uint32_t u = __float_as_uint(v);
    asm("mov.b64 %0,{%1,%1};" : "=l"(r) : "r"(u));
    return r;
}
#endif // TC_OK

// exp(2a) degree-5 Taylor (valid for |a| <~ 0.5; diagonal cancels exactly)
__device__ __forceinline__ float poly5(float a) {
    float p = fmaf(0.26666668f, a, 0.66666669f);
    p = fmaf(p, a, 1.33333337f);
    p = fmaf(p, a, 2.0f);
    p = fmaf(p, a, 2.0f);
    p = fmaf(p, a, 1.0f);
    return p;
}

// blocked-atom SW128 byte offset for (row r, 16B chunk q) in a 128-row tile
__device__ __forceinline__ uint32_t tile_off(int r, int q) {
    return ((uint32_t)(r >> 3) << 10) + ((uint32_t)(q >> 3) << 14)
         + ((uint32_t)(r & 7) << 7)
         + ((((uint32_t)(q & 7)) << 4) ^ (((uint32_t)(r & 7)) << 4));
}

// ---------------------------------------------------------------------------
// Kernel 1: normalize rows (fp32) -> bf16 (+ fp32 copy in fallback pass).
// 2 rows per warp for ILP; also resets the tail-reduction ticket.
// ---------------------------------------------------------------------------
__global__ void k_normalize(const float* __restrict__ zis,
                            const float* __restrict__ zjs) {
    if (blockIdx.x == 0 && threadIdx.x == 0) g_ticket = 0;

    int warp = threadIdx.x >> 5;
    int lane = threadIdx.x & 31;
    int rowA = blockIdx.x * 16 + warp * 2;

    #pragma unroll
    for (int rr = 0; rr < 2; rr++) {
        int row = rowA + rr;
        const float* src = (row < NHALF) ? (zjs + (size_t)row * DIMK)
                                         : (zis + (size_t)(row - NHALF) * DIMK);
        const float4* s4 = (const float4*)src;
        float4 v0 = s4[2 * lane];
        float4 v1 = s4[2 * lane + 1];

        float ss = v0.x*v0.x + v0.y*v0.y + v0.z*v0.z + v0.w*v0.w
                 + v1.x*v1.x + v1.y*v1.y + v1.z*v1.z + v1.w*v1.w;
        #pragma unroll
        for (int o = 16; o; o >>= 1) ss += __shfl_xor_sync(0xffffffffu, ss, o);
        float inv = rsqrtf(ss);

        float4 n0 = make_float4(v0.x*inv, v0.y*inv, v0.z*inv, v0.w*inv);
        float4 n1 = make_float4(v1.x*inv, v1.y*inv, v1.z*inv, v1.w*inv);

        __nv_bfloat162 h0 = __floats2bfloat162_rn(n0.x, n0.y);
        __nv_bfloat162 h1 = __floats2bfloat162_rn(n0.z, n0.w);
        __nv_bfloat162 h2 = __floats2bfloat162_rn(n1.x, n1.y);
        __nv_bfloat162 h3 = __floats2bfloat162_rn(n1.z, n1.w);
        uint4 o4;
        o4.x = *reinterpret_cast<uint32_t*>(&h0);
        o4.y = *reinterpret_cast<uint32_t*>(&h1);
        o4.z = *reinterpret_cast<uint32_t*>(&h2);
        o4.w = *reinterpret_cast<uint32_t*>(&h3);
        g_Rb4[(size_t)row * 32 + lane] = o4;

#if !TC_OK
        float4* d4 = (float4*)(g_R + (size_t)row * DIMK);
        d4[2 * lane]     = n0;
        d4[2 * lane + 1] = n1;
#endif
    }
}

// ---------------------------------------------------------------------------
// Kernel 2a: tcgen05 TS-mode fused sim-GEMM + masked exp-sum (sm_103a only).
// grid = 128: blockIdx -> (row block rb = bid>>1, col half h = bid&1).
// A: 128x256 bf16 in TMEM (cols 0..127). B: 3 smem buffers via cp.async.
// D: 3 TMEM buffers. Last CTA computes final loss in-kernel (ticket).
// ---------------------------------------------------------------------------
__global__ void __launch_bounds__(NTHREADS, 1) k_fused(float* __restrict__ out) {
#if TC_OK
    extern __shared__ __align__(1024) char smem[];
    const uint32_t sb = smem_u32(smem);
    const int t    = threadIdx.x;
    const int w    = t >> 5;
    const int lane = t & 31;

    const int rb   = blockIdx.x >> 1;
    const int h    = blockIdx.x & 1;
    const int row0 = rb * TM;

    const uint32_t mb_full0 = sb + MB_OFF;        // 3 x 8B : b_full   (count 4)
    const uint32_t mb_mma0  = sb + MB_OFF + 24;   // 3 x 8B : mma_done (count 1)
    const uint32_t mb_epi0  = sb + MB_OFF + 48;   // 3 x 8B : epi_done (count 8)

    if (t == 0) {
        #pragma unroll
        for (int i = 0; i < 3; i++) {
            mb_init(mb_full0 + 8 * i, 4);
            mb_init(mb_mma0  + 8 * i, 1);
            mb_init(mb_epi0  + 8 * i, 8);
        }
    }
    if (w == 8) tc_alloc(sb + CTRL_OFF, 512);
    __syncthreads();

    uint32_t tmem_base;
    asm volatile("ld.shared.b32 %0, [%1];" : "=r"(tmem_base) : "r"(sb + CTRL_OFF));

    // ---- A -> TMEM (threads 0..127 = warpgroup 0; row r = t). 128 bf16x2 cols.
    if (t < 128) {
        const uint4* arow = g_Rb4 + (size_t)(row0 + t) * 32;
        const uint32_t woff = ((uint32_t)(t >> 5)) << 21;
        #pragma unroll
        for (int c = 0; c < 4; c++) {
            uint32_t areg[32];
            #pragma unroll
            for (int i = 0; i < 8; i++) {
                uint4 v = arow[c * 8 + i];
                areg[4 * i]     = v.x;
                areg[4 * i + 1] = v.y;
                areg[4 * i + 2] = v.z;
                areg[4 * i + 3] = v.w;
            }
            STTM_X32(tmem_base + c * 32 + woff, areg);
        }
        TC_WAIT_ST();
        TC_FENCE_BEFORE();
    }
    __syncthreads();

    if (w < 8) {
        // ----------------- epilogue warps -----------------
        const int plane = w >> 2;              // 0: cols 0-63, 1: cols 64-127
        const int cbase = plane * 64;
        const int r_loc = (w & 3) * 32 + lane;

        const int  ct_s  = (row0 & 4095) >> 7;        // special tile index
        const bool dmode = ((row0 >> 12) == h);       // diag here vs partner
        const bool mysp  = ((r_loc >> 6) == plane);   // my cols contain it
        const int  sj    = r_loc & 63;                // local col of special

        const uint64_t C5 = pk2c(0.26666668f), C4 = pk2c(0.66666669f),
                       C3 = pk2c(1.33333337f), C2 = pk2c(2.0f),
                       C1 = pk2c(2.0f),        C0 = pk2c(1.0f);
        uint64_t s2a = pk2c(0.0f), s2b = pk2c(0.0f);
        float sacc = 0.f, ediag = 0.f, posv = 0.f;

        for (int tt = 0; tt < NTILE; tt++) {
            const int d = tt % 3;
            mb_waitp(mb_mma0 + 8 * d, (tt / 3) & 1);
            TC_FENCE_AFTER();

            uint32_t dtm = tmem_base + TMEM_D0 + d * 128 + cbase;
            uint32_t r0[32], r1[32];

            if (tt == ct_s) {
                // checked scalar path (1 of 32 tiles)
                LDTM_X32(r0, dtm);
                LDTM_X32(r1, dtm + 32);
                TC_WAIT_LD();
                TC_FENCE_BEFORE();
                if (lane == 0) mb_arrive(mb_epi0 + 8 * d);
                #pragma unroll
                for (int j = 0; j < 32; j++) {
                    float a = __uint_as_float(r0[j]);
                    float e = poly5(a);
                    if (mysp && j == sj) { if (dmode) ediag = e; else posv = 2.0f * a; }
                    sacc += e;
                }
                #pragma unroll
                for (int j = 0; j < 32; j++) {
                    float a = __uint_as_float(r1[j]);
                    float e = poly5(a);
                    if (mysp && (j + 32) == sj) { if (dmode) ediag = e; else posv = 2.0f * a; }
                    sacc += e;
                }
            } else {
                LDTM_X32(r0, dtm);
                TC_WAIT_LD();
                LDTM_X32(r1, dtm + 32);    // in flight while computing r0
                #pragma unroll
                for (int j = 0; j < 16; j++) {
                    uint64_t a2, p2;
                    PK2(a2, r0[2 * j], r0[2 * j + 1]);
                    FMA2(p2, C5, a2, C4);
                    FMA2(p2, p2, a2, C3);
                    FMA2(p2, p2, a2, C2);
                    FMA2(p2, p2, a2, C1);
                    FMA2(p2, p2, a2, C0);
                    if (j & 1) { ADD2(s2a, s2a, p2); } else { ADD2(s2b, s2b, p2); }
                }
                TC_WAIT_LD();
                TC_FENCE_BEFORE();
                if (lane == 0) mb_arrive(mb_epi0 + 8 * d);  // release TMEM early
                #pragma unroll
                for (int j = 0; j < 16; j++) {
                    uint64_t a2, p2;
                    PK2(a2, r1[2 * j], r1[2 * j + 1]);
                    FMA2(p2, C5, a2, C4);
                    FMA2(p2, p2, a2, C3);
                    FMA2(p2, p2, a2, C2);
                    FMA2(p2, p2, a2, C1);
                    FMA2(p2, p2, a2, C0);
                    if (j & 1) { ADD2(s2a, s2a, p2); } else { ADD2(s2b, s2b, p2); }
                }
            }
        }

        uint32_t alo, ahi, blo, bhi;
        UPK2(alo, ahi, s2a);
        UPK2(blo, bhi, s2b);
        float s_lane = __uint_as_float(alo) + __uint_as_float(ahi)
                     + __uint_as_float(blo) + __uint_as_float(bhi) + sacc - ediag;

        float* sbuf = (float*)smem;   // reuse B buffer 0 (all loads consumed)
        sbuf[plane * 128 + r_loc]       = s_lane;
        sbuf[256 + plane * 128 + r_loc] = posv;
    } else if (w == 8) {
        // ----------------- MMA warp (TS mode) -----------------
        for (int tt = 0; tt < NTILE; tt++) {
            const int d = tt % 3;
            if (tt >= 3) { mb_waitp(mb_epi0 + 8 * d, ((tt - 3) / 3) & 1); }
            mb_waitp(mb_full0 + 8 * d, (tt / 3) & 1);
            TC_FENCE_AFTER();
            if (elect_one()) {
                const uint64_t b_desc = mk_desc(sb + B_OFF + d * 65536);
                const uint32_t dtm = tmem_base + TMEM_D0 + d * 128;
                #pragma unroll
                for (int ks = 0; ks < 16; ks++) {
                    uint64_t doff = ((uint64_t)(ks >> 2) << 10) | ((uint64_t)(ks & 3) << 1);
                    mma_f16_ts(dtm, tmem_base + ks * 8, b_desc + doff, IDESC, ks > 0);
                }
                tc_commit(mb_mma0 + 8 * d);
            }
        }
    } else {
        // ----------------- loader warps (9..12), cp.async -----------------
        const int lt = t - 288;   // 0..127 -> one B row each
        for (int tt = 0; tt < NTILE; tt++) {
            const int d = tt % 3;
            if (tt >= 3) { mb_waitp(mb_mma0 + 8 * d, ((tt - 3) / 3) & 1); }
            const char* src = (const char*)(g_Rb4 + (size_t)(h * NHALF + tt * TN + lt) * 32);
            const uint32_t dst0 = sb + B_OFF + d * 65536;
            #pragma unroll
            for (int q = 0; q < 32; q++)
                cp_async16(dst0 + tile_off(lt, q), src + q * 16);
            cp_async_commit_wait();
            __syncwarp();
            fence_async_shared();
            if (lane == 0) mb_arrive(mb_full0 + 8 * d);
        }
    }

    __syncthreads();

    if (t < 128) {
        const float* sbuf = (const float*)smem;
        g_s[h * TWO_N + row0 + t] = sbuf[t] + sbuf[128 + t];
        g_p[h * TWO_N + row0 + t] = sbuf[256 + t] + sbuf[384 + t];
    }
    if (w == 8) tc_dealloc(tmem_base, 512);

    // ---- ticketed last-CTA final reduction ----
    __shared__ int s_last;
    __threadfence();
    __syncthreads();
    if (t == 0) s_last = (atomicAdd(&g_ticket, 1) == 127);
    __syncthreads();
    if (s_last) {
        __threadfence();
        float acc = 0.f;
        for (int i = t; i < TWO_N; i += NTHREADS) {
            float s = __ldcg(&g_s[i]) + __ldcg(&g_s[TWO_N + i]);
            float p = __ldcg(&g_p[i]) + __ldcg(&g_p[TWO_N + i]);
            acc += logf(s) - p;
        }
        #pragma unroll
        for (int o = 16; o; o >>= 1) acc += __shfl_xor_sync(0xffffffffu, acc, o);
        float* ws = (float*)smem;
        if (lane == 0) ws[w] = acc;
        __syncthreads();
        if (t == 0) {
            float tot = 0.f;
            #pragma unroll
            for (int i = 0; i < NWARPS; i++) tot += ws[i];
            out[0] = tot * (1.0f / (float)TWO_N);
        }
    }
#endif // TC_OK
}

// ---------------------------------------------------------------------------
// Kernel 2b: SIMT fallback (compiled into non-'a' passes only).
// ---------------------------------------------------------------------------
__global__ void k_fused_simt() {
#if !TC_OK
    extern __shared__ float sm[];
    float* As = sm;
    float* Bs = sm + BM * PAD;

    const int t    = threadIdx.x;
    const int row0 = blockIdx.x * BM;

    for (int idx = t; idx < BM * 64; idx += 256) {
        int r  = idx >> 6;
        int kq = idx & 63;
        float4 v = ((const float4*)(g_R + (size_t)(row0 + r) * DIMK))[kq];
        *(float4*)(As + r * PAD + kq * 4) = v;
    }

    const int tr = t >> 4;
    const int tx = t & 15;

    float s[4]   = {0.f, 0.f, 0.f, 0.f};
    float pos[4] = {0.f, 0.f, 0.f, 0.f};
    int grow[4], gpart[4];
    #pragma unroll
    for (int i = 0; i < 4; i++) {
        grow[i]  = row0 + tr + 16 * i;
        gpart[i] = (grow[i] + NHALF) & (TWO_N - 1);
    }

    for (int ct = 0; ct < TWO_N / BN; ct++) {
        __syncthreads();
        const int col0 = ct * BN;
        for (int idx = t; idx < BN * 64; idx += 256) {
            int r  = idx >> 6;
            int kq = idx & 63;
            float4 v = ((const float4*)(g_R + (size_t)(col0 + r) * DIMK))[kq];
            *(float4*)(Bs + r * PAD + kq * 4) = v;
        }
        __syncthreads();

        float acc[4][4];
        #pragma unroll
        for (int i = 0; i < 4; i++)
            #pragma unroll
            for (int j = 0; j < 4; j++) acc[i][j] = 0.f;

        #pragma unroll 4
        for (int kq = 0; kq < 64; kq++) {
            float4 a[4], b[4];
            #pragma unroll
            for (int i = 0; i < 4; i++)
                a[i] = *(const float4*)(As + (tr + 16 * i) * PAD + kq * 4);
            #pragma unroll
            for (int j = 0; j < 4; j++)
                b[j] = *(const float4*)(Bs + (tx + 16 * j) * PAD + kq * 4);
            #pragma unroll
            for (int i = 0; i < 4; i++)
                #pragma unroll
                for (int j = 0; j < 4; j++) {
                    acc[i][j] = fmaf(a[i].x, b[j].x, acc[i][j]);
                    acc[i][j] = fmaf(a[i].y, b[j].y, acc[i][j]);
                    acc[i][j] = fmaf(a[i].z, b[j].z, acc[i][j]);
                    acc[i][j] = fmaf(a[i].w, b[j].w, acc[i][j]);
                }
        }

        #pragma unroll
        for (int i = 0; i < 4; i++)
            #pragma unroll
            for (int j = 0; j < 4; j++) {
                int   gc = col0 + tx + 16 * j;
                float lg = 2.0f * acc[i][j];
                float e  = __expf(lg);
                if (gc == grow[i])  e = 0.0f;
                if (gc == gpart[i]) pos[i] = lg;
                s[i] += e;
            }
    }

    #pragma unroll
    for (int i = 0; i < 4; i++) {
        #pragma unroll
        for (int o = 8; o; o >>= 1) {
            s[i]   += __shfl_xor_sync(0xffffffffu, s[i],   o, 16);
            pos[i] += __shfl_xor_sync(0xffffffffu, pos[i], o, 16);
        }
        if (tx == 0) {
            g_s[grow[i]]         = s[i];
            g_s[TWO_N + grow[i]] = 0.f;
            g_p[grow[i]]         = pos[i];
            g_p[TWO_N + grow[i]] = 0.f;
        }
    }
#endif // !TC_OK
}

// ---------------------------------------------------------------------------
// Tail kernel: active only in the fallback pass (TC pass folds it in-kernel).
// ---------------------------------------------------------------------------
__global__ void k_loss(float* __restrict__ out) {
#if !TC_OK
    int r = blockIdx.x * 128 + threadIdx.x;
    float s = g_s[r] + g_s[TWO_N + r];
    float p = g_p[r] + g_p[TWO_N + r];
    float v = logf(s) - p;
    #pragma unroll
    for (int o = 16; o; o >>= 1) v += __shfl_xor_sync(0xffffffffu, v, o);
    __shared__ float ws[4];
    __shared__ int last;
    if ((threadIdx.x & 31) == 0) ws[threadIdx.x >> 5] = v;
    __syncthreads();
    if (threadIdx.x == 0) {
        g_partials[blockIdx.x] = ws[0] + ws[1] + ws[2] + ws[3];
        __threadfence();
        last = (atomicAdd(&g_ticket, 1) == 63);
    }
    __syncthreads();
    if (last && threadIdx.x < 32) {
        float a = __ldcg(&g_partials[threadIdx.x]) + __ldcg(&g_partials[threadIdx.x + 32]);
        #pragma unroll
        for (int o = 16; o; o >>= 1) a += __shfl_xor_sync(0xffffffffu, a, o);
        if (threadIdx.x == 0) out[0] = a * (1.0f / (float)TWO_N);
    }
#endif // !TC_OK
}

// ---------------------------------------------------------------------------
extern "C" void kernel_launch(void* const* d_in, const int* in_sizes, int n_in,
                              void* d_out, int out_size) {
    const float* zis = (const float*)d_in[0];
    const float* zjs = (const float*)d_in[1];
    float* out = (float*)d_out;

    cudaFuncSetAttribute(k_fused, cudaFuncAttributeMaxDynamicSharedMemorySize,
                         SMEM_TOTAL);
    cudaFuncSetAttribute(k_fused_simt, cudaFuncAttributeMaxDynamicSharedMemorySize,
                         SIMT_SMEM);

    k_normalize<<<TWO_N / 16, 256>>>(zis, zjs);
    k_fused<<<128, NTHREADS, SMEM_TOTAL>>>(out);     // no-op unless sm_103a pass
    k_fused_simt<<<128, 256, SIMT_SMEM>>>();         // no-op in sm_103a pass
    k_loss<<<64, 128>>>(out);                        // no-op in sm_103a pass
}

// round 9
// speedup vs baseline: 1.3468x; 1.3468x over previous
#include <cuda_runtime.h>
#include <cuda_bf16.h>
#include <cstdint>

// NT-Xent loss. Primary: tcgen05 bf16 GEMM (SS mode), TM=256 x TN=64 tiling
// (two 128-row A tiles resident in SMEM, 64-col B tiles double-buffered) +
// fused masked logsumexp, in-kernel final reduction. Fallback: SIMT fp32.

#define TWO_N   8192
#define NHALF   4096
#define DIMK    256
#define TMH     128         // rows per A tile (2 tiles per CTA = 256 rows)
#define TN      64          // cols per B tile
#define QCOLS   2048        // cols per CTA (quarter)
#define NTILE   32          // B tiles per CTA (2048 / 64)
#define NTHREADS 416        // 8 epi + 1 mma + 4 loader warps
#define NWARPS  13
#define IDESC64 0x8100490u  // f32 accum, bf16 x bf16, M=128, N=64

#define A0_OFF  0           // 64KB A tile 0 (rows row0..row0+127)
#define A1_OFF  65536       // 64KB A tile 1 (rows row0+128..row0+255)
#define B_OFF   131072      // two 32KB B buffers
#define CTRL_OFF 196608     // tmem ptr (4B)
#define MB_OFF  196616      // mbarriers: b_full[2], mma[4], epi[4] (8B each)
#define SMEM_TOTAL 196704

#define TMEM_D0 0           // D buffers: 4 x 128 cols (A0 at +0, A1 at +64)

// SIMT fallback tiling
#define BM      64
#define BN      64
#define PAD     260
#define SIMT_SMEM ((BM + BN) * PAD * 4)

// Feature gate: tcgen05 only exists in the arch-specific sm_103a pass.
#if defined(__CUDA_ARCH__) && (defined(__CUDA_ARCH_FEAT_SM103_ALL) || \
    (defined(__CUDA_ARCH_SPECIFIC__) && (__CUDA_ARCH_SPECIFIC__ == 1030)))
#define TC_OK 1
#else
#define TC_OK 0
#endif

__device__ uint4 g_Rb4[TWO_N * DIMK / 8];   // bf16 normalized reps (4 MB)
__device__ float g_R[TWO_N * DIMK];         // fp32 normalized reps (fallback)
__device__ float g_s[4 * TWO_N];            // per-quarter exp sums
__device__ float g_p[4 * TWO_N];            // per-quarter positive logits
__device__ float g_partials[64];
__device__ int   g_ticket;

// ---------------- generic helpers ----------------
__device__ __forceinline__ uint32_t smem_u32(const void* p) {
    uint32_t a;
    asm("{ .reg .u64 t; cvta.to.shared.u64 t, %1; cvt.u32.u64 %0, t; }" : "=r"(a) : "l"(p));
    return a;
}

#if TC_OK
// ---------------- tcgen05 / PTX helpers (sm_103a pass only) ----------------
__device__ __forceinline__ uint32_t elect_one() {
    uint32_t p;
    asm volatile("{ .reg .pred p; elect.sync _|p, 0xFFFFFFFF; selp.b32 %0,1,0,p; }" : "=r"(p));
    return p;
}
__device__ __forceinline__ void mb_init(uint32_t mb, uint32_t cnt) {
    asm volatile("mbarrier.init.shared.b64 [%0], %1;" :: "r"(mb), "r"(cnt) : "memory");
}
__device__ __forceinline__ void mb_arrive(uint32_t mb) {
    asm volatile("mbarrier.arrive.shared.b64 _, [%0];" :: "r"(mb) : "memory");
}
__device__ __forceinline__ void mb_waitp(uint32_t mb, uint32_t parity) {
    asm volatile(
        "{\n\t.reg .pred P1;\n\t"
        "WL_%=:\n\t"
        "mbarrier.try_wait.parity.acquire.cta.shared::cta.b64 P1, [%0], %1, 0x989680;\n\t"
        "@P1 bra.uni WD_%=;\n\t"
        "bra.uni WL_%=;\n\t"
        "WD_%=:\n\t}"
        :: "r"(mb), "r"(parity) : "memory");
}
__device__ __forceinline__ void fence_async_shared() {
    asm volatile("fence.proxy.async.shared::cta;" ::: "memory");
}
__device__ __forceinline__ void cp_async16(uint32_t dst, const void* src) {
    asm volatile("cp.async.cg.shared.global [%0], [%1], 16;"
                 :: "r"(dst), "l"(src) : "memory");
}
__device__ __forceinline__ void cp_async_commit_wait() {
    asm volatile("cp.async.commit_group;" ::: "memory");
    asm volatile("cp.async.wait_group 0;" ::: "memory");
}
#define TC_FENCE_AFTER()  asm volatile("tcgen05.fence::after_thread_sync;" ::: "memory")
#define TC_FENCE_BEFORE() asm volatile("tcgen05.fence::before_thread_sync;" ::: "memory")
#define TC_WAIT_LD()      asm volatile("tcgen05.wait::ld.sync.aligned;" ::: "memory")

__device__ __forceinline__ void tc_alloc(uint32_t smem_res, uint32_t ncols) {
    asm volatile("tcgen05.alloc.cta_group::1.sync.aligned.shared::cta.b32 [%0], %1;"
                 :: "r"(smem_res), "r"(ncols) : "memory");
}
__device__ __forceinline__ void tc_dealloc(uint32_t tmem, uint32_t ncols) {
    asm volatile("tcgen05.dealloc.cta_group::1.sync.aligned.b32 %0, %1;" :: "r"(tmem), "r"(ncols));
}
__device__ __forceinline__ void tc_commit(uint32_t mb) {
    asm volatile("tcgen05.commit.cta_group::1.mbarrier::arrive::one.shared::cluster.b64 [%0];"
                 :: "r"(mb) : "memory");
}
__device__ __forceinline__ void mma_f16_ss(uint32_t d, uint64_t a, uint64_t b,
                                           uint32_t idesc, uint32_t en) {
    asm volatile(
        "{\n\t.reg .pred p;\n\tsetp.ne.u32 p, %5, 0;\n\t"
        "tcgen05.mma.cta_group::1.kind::f16 [%0], %1, %2, %3, {%4,%4,%4,%4}, p;\n\t}"
        :: "r"(d), "l"(a), "l"(b), "r"(idesc), "r"(0u), "r"(en) : "memory");
}

#define LDTM_X32(r, tmem) \
    asm volatile("tcgen05.ld.sync.aligned.32x32b.x32.b32 " \
        "{%0,%1,%2,%3,%4,%5,%6,%7,%8,%9,%10,%11,%12,%13,%14,%15," \
        "%16,%17,%18,%19,%20,%21,%22,%23,%24,%25,%26,%27,%28,%29,%30,%31}, [%32];" \
        : "=r"((r)[0]),"=r"((r)[1]),"=r"((r)[2]),"=r"((r)[3]),"=r"((r)[4]),"=r"((r)[5]), \
          "=r"((r)[6]),"=r"((r)[7]),"=r"((r)[8]),"=r"((r)[9]),"=r"((r)[10]),"=r"((r)[11]), \
          "=r"((r)[12]),"=r"((r)[13]),"=r"((r)[14]),"=r"((r)[15]),"=r"((r)[16]),"=r"((r)[17]), \
          "=r"((r)[18]),"=r"((r)[19]),"=r"((r)[20]),"=r"((r)[21]),"=r"((r)[22]),"=r"((r)[23]), \
          "=r"((r)[24]),"=r"((r)[25]),"=r"((r)[26]),"=r"((r)[27]),"=r"((r)[28]),"=r"((r)[29]), \
          "=r"((r)[30]),"=r"((r)[31]) : "r"(tmem))

// SW128 base descriptor (version=1, LBO=1, SBO=64) + start address
__device__ __forceinline__ uint64_t mk_desc(uint32_t addr) {
    uint64_t base = (uint64_t(2) << 61) | (uint64_t(1) << 46) | (uint64_t(64) << 32)
                  | (uint64_t(1) << 16);
    return base | ((uint64_t)(addr >> 4) & 0x3FFF);
}

// packed f32x2 helpers
#define PK2(d, lo, hi) asm("mov.b64 %0,{%1,%2};" : "=l"(d) : "r"(lo), "r"(hi))
#define UPK2(lo, hi, s) asm("mov.b64 {%0,%1},%2;" : "=r"(lo), "=r"(hi) : "l"(s))
#define FMA2(d, a, b, c) asm("fma.rn.f32x2 %0,%1,%2,%3;" : "=l"(d) : "l"(a), "l"(b), "l"(c))
#define ADD2(d, a, b)    asm("add.rn.f32x2 %0,%1,%2;" : "=l"(d) : "l"(a), "l"(b))
__device__ __forceinline__ uint64_t pk2c(float v) {
    uint64_t r; uint32_t u = __float_as_uint(v);
    asm("mov.b64 %0,{%1,%1};" : "=l"(r) : "r"(u));
    return r;
}
#endif // TC_OK

// exp(2a) degree-5 Taylor (valid for |a| <~ 0.5; diagonal cancels exactly)
__device__ __forceinline__ float poly5(float a) {
    float p = fmaf(0.26666668f, a, 0.66666669f);
    p = fmaf(p, a, 1.33333337f);
    p = fmaf(p, a, 2.0f);
    p = fmaf(p, a, 2.0f);
    p = fmaf(p, a, 1.0f);
    return p;
}

// blocked-atom SW128 byte offset, 128-row tile (16 atom-rows, atom-col stride 16KB)
__device__ __forceinline__ uint32_t tile_off128(int r, int q) {
    return ((uint32_t)(r >> 3) << 10) + ((uint32_t)(q >> 3) << 14)
         + ((uint32_t)(r & 7) << 7)
         + ((((uint32_t)(q & 7)) << 4) ^ (((uint32_t)(r & 7)) << 4));
}
// blocked-atom SW128 byte offset, 64-row tile (8 atom-rows, atom-col stride 8KB)
__device__ __forceinline__ uint32_t tile_off64(int r, int q) {
    return ((uint32_t)(r >> 3) << 10) + ((uint32_t)(q >> 3) << 13)
         + ((uint32_t)(r & 7) << 7)
         + ((((uint32_t)(q & 7)) << 4) ^ (((uint32_t)(r & 7)) << 4));
}

// ---------------------------------------------------------------------------
// Kernel 1: normalize rows (fp32) -> bf16 (+ fp32 copy in fallback pass).
// 2 rows per warp for ILP; also resets the tail-reduction ticket.
// ---------------------------------------------------------------------------
__global__ void k_normalize(const float* __restrict__ zis,
                            const float* __restrict__ zjs) {
    if (blockIdx.x == 0 && threadIdx.x == 0) g_ticket = 0;

    int warp = threadIdx.x >> 5;
    int lane = threadIdx.x & 31;
    int rowA = blockIdx.x * 16 + warp * 2;

    #pragma unroll
    for (int rr = 0; rr < 2; rr++) {
        int row = rowA + rr;
        const float* src = (row < NHALF) ? (zjs + (size_t)row * DIMK)
                                         : (zis + (size_t)(row - NHALF) * DIMK);
        const float4* s4 = (const float4*)src;
        float4 v0 = s4[2 * lane];
        float4 v1 = s4[2 * lane + 1];

        float ss = v0.x*v0.x + v0.y*v0.y + v0.z*v0.z + v0.w*v0.w
                 + v1.x*v1.x + v1.y*v1.y + v1.z*v1.z + v1.w*v1.w;
        #pragma unroll
        for (int o = 16; o; o >>= 1) ss += __shfl_xor_sync(0xffffffffu, ss, o);
        float inv = rsqrtf(ss);

        float4 n0 = make_float4(v0.x*inv, v0.y*inv, v0.z*inv, v0.w*inv);
        float4 n1 = make_float4(v1.x*inv, v1.y*inv, v1.z*inv, v1.w*inv);

        __nv_bfloat162 h0 = __floats2bfloat162_rn(n0.x, n0.y);
        __nv_bfloat162 h1 = __floats2bfloat162_rn(n0.z, n0.w);
        __nv_bfloat162 h2 = __floats2bfloat162_rn(n1.x, n1.y);
        __nv_bfloat162 h3 = __floats2bfloat162_rn(n1.z, n1.w);
        uint4 o4;
        o4.x = *reinterpret_cast<uint32_t*>(&h0);
        o4.y = *reinterpret_cast<uint32_t*>(&h1);
        o4.z = *reinterpret_cast<uint32_t*>(&h2);
        o4.w = *reinterpret_cast<uint32_t*>(&h3);
        g_Rb4[(size_t)row * 32 + lane] = o4;

#if !TC_OK
        float4* d4 = (float4*)(g_R + (size_t)row * DIMK);
        d4[2 * lane]     = n0;
        d4[2 * lane + 1] = n1;
#endif
    }
}

// ---------------------------------------------------------------------------
// Kernel 2a: tcgen05 SS fused sim-GEMM, TM=256 x TN=64 (sm_103a pass only).
// grid = 128: rb = bid>>2 (32 row-blocks of 256), h = bid&3 (col quarter).
// A: two 128-row tiles in SMEM. B: two 32KB smem buffers via cp.async.
// D: 4 TMEM buffers of 128 cols (A0 -> +0..63, A1 -> +64..127).
// ---------------------------------------------------------------------------
__global__ void __launch_bounds__(NTHREADS, 1) k_fused(float* __restrict__ out) {
#if TC_OK
    extern __shared__ __align__(1024) char smem[];
    const uint32_t sb = smem_u32(smem);
    const int t    = threadIdx.x;
    const int w    = t >> 5;
    const int lane = t & 31;

    const int rb   = blockIdx.x >> 2;
    const int h    = blockIdx.x & 3;
    const int row0 = rb * 256;
    const int col0 = h * QCOLS;

    const uint32_t mb_full0 = sb + MB_OFF;        // 2 x 8B : b_full   (count 4)
    const uint32_t mb_mma0  = sb + MB_OFF + 16;   // 4 x 8B : mma_done (count 1)
    const uint32_t mb_epi0  = sb + MB_OFF + 48;   // 4 x 8B : epi_done (count 8)

    if (t == 0) {
        mb_init(mb_full0, 4);  mb_init(mb_full0 + 8, 4);
        #pragma unroll
        for (int i = 0; i < 4; i++) { mb_init(mb_mma0 + 8 * i, 1); mb_init(mb_epi0 + 8 * i, 8); }
    }
    if (w == 8) tc_alloc(sb + CTRL_OFF, 512);

    // A tiles load (all threads): 256 rows, swizzled blocked-atom, 2 tiles.
    for (int idx = t; idx < 256 * 32; idx += NTHREADS) {
        int r = idx >> 5, q = idx & 31;
        uint4 v = g_Rb4[(size_t)(row0 + r) * 32 + q];
        uint32_t base = (r < 128) ? A0_OFF : A1_OFF;
        *(uint4*)(smem + base + tile_off128(r & 127, q)) = v;
    }
    fence_async_shared();
    __syncthreads();

    uint32_t tmem_base;
    asm volatile("ld.shared.b32 %0, [%1];" : "=r"(tmem_base) : "r"(sb + CTRL_OFF));

    if (w < 8) {
        // ----------------- epilogue warps -----------------
        const int plane = w >> 2;              // A-half: 0 -> rows +0, 1 -> rows +128
        const int r_loc = (w & 3) * 32 + lane; // TMEM lane
        const int rowbase = row0 + plane * 128 + (w & 3) * 32;  // warp's first row

        // special element (diag or partner) for this warp's rows, if in quarter h
        const bool diag_here = ((rowbase >> 11) == h);
        const bool part_here = ((((rowbase + NHALF) & (TWO_N - 1)) >> 11) == h);
        const int  ct_s  = (diag_here || part_here) ? ((rowbase & (QCOLS - 1)) >> 6) : -1;
        const bool dmode = diag_here;
        const int  sj    = r_loc & 63;         // per-lane local col of special

        const uint64_t C5 = pk2c(0.26666668f), C4 = pk2c(0.66666669f),
                       C3 = pk2c(1.33333337f), C2 = pk2c(2.0f),
                       C1 = pk2c(2.0f),        C0 = pk2c(1.0f);
        uint64_t s2a = pk2c(0.0f), s2b = pk2c(0.0f);
        float sacc = 0.f, ediag = 0.f, posv = 0.f;

        for (int tt = 0; tt < NTILE; tt++) {
            const int d = tt & 3;
            mb_waitp(mb_mma0 + 8 * d, (tt >> 2) & 1);
            TC_FENCE_AFTER();

            uint32_t dtm = tmem_base + d * 128 + plane * 64;
            uint32_t r0[32], r1[32];

            if (tt == ct_s) {
                // checked scalar path (at most 1 of 32 tiles per warp)
                LDTM_X32(r0, dtm);
                LDTM_X32(r1, dtm + 32);
                TC_WAIT_LD();
                TC_FENCE_BEFORE();
                if (lane == 0) mb_arrive(mb_epi0 + 8 * d);
                #pragma unroll
                for (int j = 0; j < 32; j++) {
                    float a = __uint_as_float(r0[j]);
                    float e = poly5(a);
                    if (j == sj) { if (dmode) ediag = e; else posv = 2.0f * a; }
                    sacc += e;
                }
                #pragma unroll
                for (int j = 0; j < 32; j++) {
                    float a = __uint_as_float(r1[j]);
                    float e = poly5(a);
                    if ((j + 32) == sj) { if (dmode) ediag = e; else posv = 2.0f * a; }
                    sacc += e;
                }
            } else {
                LDTM_X32(r0, dtm);
                TC_WAIT_LD();
                LDTM_X32(r1, dtm + 32);    // in flight while computing r0
                #pragma unroll
                for (int j = 0; j < 16; j++) {
                    uint64_t a2, p2;
                    PK2(a2, r0[2 * j], r0[2 * j + 1]);
                    FMA2(p2, C5, a2, C4);
                    FMA2(p2, p2, a2, C3);
                    FMA2(p2, p2, a2, C2);
                    FMA2(p2, p2, a2, C1);
                    FMA2(p2, p2, a2, C0);
                    if (j & 1) { ADD2(s2a, s2a, p2); } else { ADD2(s2b, s2b, p2); }
                }
                TC_WAIT_LD();
                TC_FENCE_BEFORE();
                if (lane == 0) mb_arrive(mb_epi0 + 8 * d);  // release TMEM early
                #pragma unroll
                for (int j = 0; j < 16; j++) {
                    uint64_t a2, p2;
                    PK2(a2, r1[2 * j], r1[2 * j + 1]);
                    FMA2(p2, C5, a2, C4);
                    FMA2(p2, p2, a2, C3);
                    FMA2(p2, p2, a2, C2);
                    FMA2(p2, p2, a2, C1);
                    FMA2(p2, p2, a2, C0);
                    if (j & 1) { ADD2(s2a, s2a, p2); } else { ADD2(s2b, s2b, p2); }
                }
            }
        }

        uint32_t alo, ahi, blo, bhi;
        UPK2(alo, ahi, s2a);
        UPK2(blo, bhi, s2b);
        float s_lane = __uint_as_float(alo) + __uint_as_float(ahi)
                     + __uint_as_float(blo) + __uint_as_float(bhi) + sacc - ediag;

        float* sbuf = (float*)smem;   // reuse A0 region (all MMA A-reads done)
        sbuf[plane * 128 + r_loc]       = s_lane;   // 256 rows
        sbuf[256 + plane * 128 + r_loc] = posv;
    } else if (w == 8) {
        // ----------------- MMA warp (SS mode, 2 MMAs per B tile) -----------------
        const uint64_t a0_desc = mk_desc(sb + A0_OFF);
        const uint64_t a1_desc = mk_desc(sb + A1_OFF);
        for (int tt = 0; tt < NTILE; tt++) {
            const int b = tt & 1;
            const int d = tt & 3;
            if (tt >= 4) { mb_waitp(mb_epi0 + 8 * d, ((tt - 4) >> 2) & 1); }
            mb_waitp(mb_full0 + 8 * b, (tt >> 1) & 1);
            TC_FENCE_AFTER();
            if (elect_one()) {
                const uint64_t b_desc = mk_desc(sb + B_OFF + b * 32768);
                const uint32_t dtm = tmem_base + d * 128;
                #pragma unroll
                for (int ks = 0; ks < 16; ks++) {
                    uint64_t da = ((uint64_t)(ks >> 2) << 10) | ((uint64_t)(ks & 3) << 1);
                    uint64_t db = ((uint64_t)(ks >> 2) << 9)  | ((uint64_t)(ks & 3) << 1);
                    mma_f16_ss(dtm,      a0_desc + da, b_desc + db, IDESC64, ks > 0);
                    mma_f16_ss(dtm + 64, a1_desc + da, b_desc + db, IDESC64, ks > 0);
                }
                tc_commit(mb_mma0 + 8 * d);
            }
        }
    } else {
        // ----------------- loader warps (9..12), cp.async -----------------
        const int lt   = t - 288;        // 0..127
        const int brow = lt >> 1;        // B row 0..63
        const int qh   = (lt & 1) * 16;  // chunk half: q in [qh, qh+16)
        for (int tt = 0; tt < NTILE; tt++) {
            const int b = tt & 1;
            if (tt >= 2) { mb_waitp(mb_mma0 + 8 * ((tt - 2) & 3), ((tt - 2) >> 2) & 1); }
            const char* src = (const char*)(g_Rb4 + (size_t)(col0 + tt * TN + brow) * 32) + qh * 16;
            const uint32_t dst0 = sb + B_OFF + b * 32768;
            #pragma unroll
            for (int q = 0; q < 16; q++)
                cp_async16(dst0 + tile_off64(brow, qh + q), src + q * 16);
            cp_async_commit_wait();
            __syncwarp();
            fence_async_shared();
            if (lane == 0) mb_arrive(mb_full0 + 8 * b);
        }
    }

    __syncthreads();

    if (t < 256) {
        const float* sbuf = (const float*)smem;
        g_s[h * TWO_N + row0 + t] = sbuf[t];
        g_p[h * TWO_N + row0 + t] = sbuf[256 + t];
    }
    if (w == 8) tc_dealloc(tmem_base, 512);

    // ---- ticketed last-CTA final reduction ----
    __shared__ int s_last;
    __threadfence();
    __syncthreads();
    if (t == 0) s_last = (atomicAdd(&g_ticket, 1) == 127);
    __syncthreads();
    if (s_last) {
        __threadfence();
        float acc = 0.f;
        for (int i = t; i < TWO_N; i += NTHREADS) {
            float s = __ldcg(&g_s[i])             + __ldcg(&g_s[TWO_N + i])
                    + __ldcg(&g_s[2 * TWO_N + i]) + __ldcg(&g_s[3 * TWO_N + i]);
            float p = __ldcg(&g_p[i])             + __ldcg(&g_p[TWO_N + i])
                    + __ldcg(&g_p[2 * TWO_N + i]) + __ldcg(&g_p[3 * TWO_N + i]);
            acc += logf(s) - p;
        }
        #pragma unroll
        for (int o = 16; o; o >>= 1) acc += __shfl_xor_sync(0xffffffffu, acc, o);
        float* ws = (float*)smem;
        __syncthreads();
        if (lane == 0) ws[w] = acc;
        __syncthreads();
        if (t == 0) {
            float tot = 0.f;
            #pragma unroll
            for (int i = 0; i < NWARPS; i++) tot += ws[i];
            out[0] = tot * (1.0f / (float)TWO_N);
        }
    }
#endif // TC_OK
}

// ---------------------------------------------------------------------------
// Kernel 2b: SIMT fallback (compiled into non-'a' passes only).
// ---------------------------------------------------------------------------
__global__ void k_fused_simt() {
#if !TC_OK
    extern __shared__ float sm[];
    float* As = sm;
    float* Bs = sm + BM * PAD;

    const int t    = threadIdx.x;
    const int row0 = blockIdx.x * BM;

    for (int idx = t; idx < BM * 64; idx += 256) {
        int r  = idx >> 6;
        int kq = idx & 63;
        float4 v = ((const float4*)(g_R + (size_t)(row0 + r) * DIMK))[kq];
        *(float4*)(As + r * PAD + kq * 4) = v;
    }

    const int tr = t >> 4;
    const int tx = t & 15;

    float s[4]   = {0.f, 0.f, 0.f, 0.f};
    float pos[4] = {0.f, 0.f, 0.f, 0.f};
    int grow[4], gpart[4];
    #pragma unroll
    for (int i = 0; i < 4; i++) {
        grow[i]  = row0 + tr + 16 * i;
        gpart[i] = (grow[i] + NHALF) & (TWO_N - 1);
    }

    for (int ct = 0; ct < TWO_N / BN; ct++) {
        __syncthreads();
        const int col0 = ct * BN;
        for (int idx = t; idx < BN * 64; idx += 256) {
            int r  = idx >> 6;
            int kq = idx & 63;
            float4 v = ((const float4*)(g_R + (size_t)(col0 + r) * DIMK))[kq];
            *(float4*)(Bs + r * PAD + kq * 4) = v;
        }
        __syncthreads();

        float acc[4][4];
        #pragma unroll
        for (int i = 0; i < 4; i++)
            #pragma unroll
            for (int j = 0; j < 4; j++) acc[i][j] = 0.f;

        #pragma unroll 4
        for (int kq = 0; kq < 64; kq++) {
            float4 a[4], b[4];
            #pragma unroll
            for (int i = 0; i < 4; i++)
                a[i] = *(const float4*)(As + (tr + 16 * i) * PAD + kq * 4);
            #pragma unroll
            for (int j = 0; j < 4; j++)
                b[j] = *(const float4*)(Bs + (tx + 16 * j) * PAD + kq * 4);
            #pragma unroll
            for (int i = 0; i < 4; i++)
                #pragma unroll
                for (int j = 0; j < 4; j++) {
                    acc[i][j] = fmaf(a[i].x, b[j].x, acc[i][j]);
                    acc[i][j] = fmaf(a[i].y, b[j].y, acc[i][j]);
                    acc[i][j] = fmaf(a[i].z, b[j].z, acc[i][j]);
                    acc[i][j] = fmaf(a[i].w, b[j].w, acc[i][j]);
                }
        }

        #pragma unroll
        for (int i = 0; i < 4; i++)
            #pragma unroll
            for (int j = 0; j < 4; j++) {
                int   gc = col0 + tx + 16 * j;
                float lg = 2.0f * acc[i][j];
                float e  = __expf(lg);
                if (gc == grow[i])  e = 0.0f;
                if (gc == gpart[i]) pos[i] = lg;
                s[i] += e;
            }
    }

    #pragma unroll
    for (int i = 0; i < 4; i++) {
        #pragma unroll
        for (int o = 8; o; o >>= 1) {
            s[i]   += __shfl_xor_sync(0xffffffffu, s[i],   o, 16);
            pos[i] += __shfl_xor_sync(0xffffffffu, pos[i], o, 16);
        }
        if (tx == 0) {
            g_s[grow[i]] = s[i];
            g_p[grow[i]] = pos[i];
            #pragma unroll
            for (int qq = 1; qq < 4; qq++) {
                g_s[qq * TWO_N + grow[i]] = 0.f;
                g_p[qq * TWO_N + grow[i]] = 0.f;
            }
        }
    }
#endif // !TC_OK
}

// ---------------------------------------------------------------------------
// Tail kernel: active only in the fallback pass (TC pass folds it in-kernel).
// ---------------------------------------------------------------------------
__global__ void k_loss(float* __restrict__ out) {
#if !TC_OK
    int r = blockIdx.x * 128 + threadIdx.x;
    float s = g_s[r] + g_s[TWO_N + r] + g_s[2 * TWO_N + r] + g_s[3 * TWO_N + r];
    float p = g_p[r] + g_p[TWO_N + r] + g_p[2 * TWO_N + r] + g_p[3 * TWO_N + r];
    float v = logf(s) - p;
    #pragma unroll
    for (int o = 16; o; o >>= 1) v += __shfl_xor_sync(0xffffffffu, v, o);
    __shared__ float ws[4];
    __shared__ int last;
    if ((threadIdx.x & 31) == 0) ws[threadIdx.x >> 5] = v;
    __syncthreads();
    if (threadIdx.x == 0) {
        g_partials[blockIdx.x] = ws[0] + ws[1] + ws[2] + ws[3];
        __threadfence();
        last = (atomicAdd(&g_ticket, 1) == 63);
    }
    __syncthreads();
    if (last && threadIdx.x < 32) {
        float a = __ldcg(&g_partials[threadIdx.x]) + __ldcg(&g_partials[threadIdx.x + 32]);
        #pragma unroll
        for (int o = 16; o; o >>= 1) a += __shfl_xor_sync(0xffffffffu, a, o);
        if (threadIdx.x == 0) out[0] = a * (1.0f / (float)TWO_N);
    }
#endif // !TC_OK
}

// ---------------------------------------------------------------------------
extern "C" void kernel_launch(void* const* d_in, const int* in_sizes, int n_in,
                              void* d_out, int out_size) {
    const float* zis = (const float*)d_in[0];
    const float* zjs = (const float*)d_in[1];
    float* out = (float*)d_out;

    cudaFuncSetAttribute(k_fused, cudaFuncAttributeMaxDynamicSharedMemorySize,
                         SMEM_TOTAL);
    cudaFuncSetAttribute(k_fused_simt, cudaFuncAttributeMaxDynamicSharedMemorySize,
                         SIMT_SMEM);

    k_normalize<<<TWO_N / 16, 256>>>(zis, zjs);
    k_fused<<<128, NTHREADS, SMEM_TOTAL>>>(out);     // no-op unless sm_103a pass
    k_fused_simt<<<128, 256, SIMT_SMEM>>>();         // no-op in sm_103a pass
    k_loss<<<64, 128>>>(out);                        // no-op in sm_103a pass
}